// round 2
// baseline (speedup 1.0000x reference)
#include <cuda_runtime.h>
#include <cuda_bf16.h>

#define MM 6
#define NN 3

__device__ __forceinline__ void mat33_mul(const float* __restrict__ A,
                                          const float* __restrict__ B,
                                          float* __restrict__ C) {
    #pragma unroll
    for (int i = 0; i < 3; i++) {
        #pragma unroll
        for (int j = 0; j < 3; j++) {
            float acc = A[i*3+0] * B[0*3+j];
            acc = fmaf(A[i*3+1], B[1*3+j], acc);
            acc = fmaf(A[i*3+2], B[2*3+j], acc);
            C[i*3+j] = acc;
        }
    }
}

__global__ void __launch_bounds__(256)
transop_expm_kernel(const float* __restrict__ c,
                    const float* __restrict__ x,
                    const float* __restrict__ psi,
                    float* __restrict__ out,
                    int B)
{
    __shared__ float s_psi[MM * NN * NN];   // 54 floats
    int tid = threadIdx.x;
    if (tid < MM * NN * NN) s_psi[tid] = psi[tid];
    __syncthreads();

    int b = blockIdx.x * blockDim.x + tid;
    if (b >= B) return;

    // ---- load c[b, 0..5] (24 bytes, 8B-aligned -> 3x float2) ----
    const float2* c2 = reinterpret_cast<const float2*>(c) + (size_t)b * 3;
    float2 ca = c2[0], cb = c2[1], cd = c2[2];
    float cc[MM] = {ca.x, ca.y, cb.x, cb.y, cd.x, cd.y};

    // ---- T = sum_m c[m] * psi[m]  (3x3) ----
    float T[9];
    #pragma unroll
    for (int i = 0; i < 9; i++) {
        float acc = cc[0] * s_psi[0*9 + i];
        #pragma unroll
        for (int m = 1; m < MM; m++)
            acc = fmaf(cc[m], s_psi[m*9 + i], acc);
        T[i] = acc;
    }

    // ---- scaling: pick s so ||T/2^s||_F <= 0.5 ----
    float n2 = 0.f;
    #pragma unroll
    for (int i = 0; i < 9; i++) n2 = fmaf(T[i], T[i], n2);
    float nrm = sqrtf(n2);
    int s = 0;
    if (nrm > 0.5f) {
        s = ilogbf(nrm) + 2;     // nrm in [2^e, 2^{e+1}) -> nrm*2^-(e+2) in [0.25,0.5)
        if (s < 0) s = 0;
        if (s > 12) s = 12;      // safety clamp
    }
    float scale = ldexpf(1.0f, -s);

    float A[9];
    #pragma unroll
    for (int i = 0; i < 9; i++) A[i] = T[i] * scale;

    // ---- degree-8 Taylor via Horner: E = I + A(I + A/2(I + ... (I + A/8)))
    const float inv_k[8] = {0.f,                 // unused slot (k=0)
                            1.0f,                // 1/1
                            0.5f,                // 1/2
                            0.3333333333333333f, // 1/3
                            0.25f,               // 1/4
                            0.2f,                // 1/5
                            0.16666666666666666f,// 1/6
                            0.14285714285714285f // 1/7
                           };
    float P[9], Q[9];
    #pragma unroll
    for (int i = 0; i < 9; i++) P[i] = A[i] * 0.125f;   // A/8
    P[0] += 1.f; P[4] += 1.f; P[8] += 1.f;

    #pragma unroll
    for (int k = 7; k >= 1; k--) {
        mat33_mul(A, P, Q);
        float invk = inv_k[k];   // compile-time constant after unroll
        #pragma unroll
        for (int i = 0; i < 9; i++) P[i] = Q[i] * invk;
        P[0] += 1.f; P[4] += 1.f; P[8] += 1.f;
    }

    // ---- repeated squaring: E = P^(2^s) ----
    for (int it = 0; it < s; it++) {
        mat33_mul(P, P, Q);
        #pragma unroll
        for (int i = 0; i < 9; i++) P[i] = Q[i];
    }

    // ---- y = E @ x[b] ----
    const float* xb = x + (size_t)b * 3;
    float x0 = xb[0], x1 = xb[1], x2 = xb[2];

    float* ob = out + (size_t)b * 3;
    ob[0] = fmaf(P[0], x0, fmaf(P[1], x1, P[2] * x2));
    ob[1] = fmaf(P[3], x0, fmaf(P[4], x1, P[5] * x2));
    ob[2] = fmaf(P[6], x0, fmaf(P[7], x1, P[8] * x2));
}

extern "C" void kernel_launch(void* const* d_in, const int* in_sizes, int n_in,
                              void* d_out, int out_size) {
    const float* c   = (const float*)d_in[0];   // (B, 6)
    const float* x   = (const float*)d_in[1];   // (B, 3, 1)
    const float* psi = (const float*)d_in[2];   // (6, 3, 3)
    float* out = (float*)d_out;                 // (B, 3, 1)

    int B = in_sizes[0] / MM;
    int threads = 256;
    int blocks = (B + threads - 1) / threads;
    transop_expm_kernel<<<blocks, threads>>>(c, x, psi, out, B);
}

// round 4
// speedup vs baseline: 1.1340x; 1.1340x over previous
#include <cuda_runtime.h>
#include <cuda_bf16.h>

#define MM 6
#define NN 3

// C = A * B
__device__ __forceinline__ void mat33_mul(const float* __restrict__ A,
                                          const float* __restrict__ B,
                                          float* __restrict__ C) {
    #pragma unroll
    for (int i = 0; i < 3; i++) {
        #pragma unroll
        for (int j = 0; j < 3; j++) {
            float acc = A[i*3+0] * B[0*3+j];
            acc = fmaf(A[i*3+1], B[1*3+j], acc);
            acc = fmaf(A[i*3+2], B[2*3+j], acc);
            C[i*3+j] = acc;
        }
    }
}

// C = Acc + A * B  (accumulator-initialized matmul)
__device__ __forceinline__ void mat33_mul_acc(const float* __restrict__ A,
                                              const float* __restrict__ B,
                                              const float* __restrict__ Acc,
                                              float* __restrict__ C) {
    #pragma unroll
    for (int i = 0; i < 3; i++) {
        #pragma unroll
        for (int j = 0; j < 3; j++) {
            float acc = Acc[i*3+j];
            acc = fmaf(A[i*3+0], B[0*3+j], acc);
            acc = fmaf(A[i*3+1], B[1*3+j], acc);
            acc = fmaf(A[i*3+2], B[2*3+j], acc);
            C[i*3+j] = acc;
        }
    }
}

__global__ void __launch_bounds__(256)
transop_expm_kernel(const float* __restrict__ c,
                    const float* __restrict__ x,
                    const float* __restrict__ psi,
                    float* __restrict__ out,
                    int B)
{
    __shared__ float s_psi[MM * NN * NN];   // 54 floats
    int tid = threadIdx.x;
    if (tid < MM * NN * NN) s_psi[tid] = psi[tid];
    __syncthreads();

    int b = blockIdx.x * blockDim.x + tid;
    if (b >= B) return;

    // ---- load c[b, 0..5] (24 bytes, 8B-aligned -> 3x float2) ----
    const float2* c2 = reinterpret_cast<const float2*>(c) + (size_t)b * 3;
    float2 ca = c2[0], cb = c2[1], cd = c2[2];
    float cc[MM] = {ca.x, ca.y, cb.x, cb.y, cd.x, cd.y};

    // ---- T = sum_m c[m] * psi[m]  (3x3) ----
    float A[9];
    #pragma unroll
    for (int i = 0; i < 9; i++) {
        float acc = cc[0] * s_psi[0*9 + i];
        #pragma unroll
        for (int m = 1; m < MM; m++)
            acc = fmaf(cc[m], s_psi[m*9 + i], acc);
        A[i] = acc;
    }

    // ---- scaling: pick s so ||A/2^s||_F < 1.0 ----
    float n2 = 0.f;
    #pragma unroll
    for (int i = 0; i < 9; i++) n2 = fmaf(A[i], A[i], n2);
    float nrm = sqrtf(n2);
    int s = 0;
    if (nrm > 1.0f) {
        s = ilogbf(nrm) + 1;     // nrm in [2^e,2^{e+1}) -> nrm*2^-(e+1) in [0.5,1)
        if (s < 0) s = 0;
        if (s > 14) s = 14;      // safety clamp
    }
    float scale = ldexpf(1.0f, -s);
    #pragma unroll
    for (int i = 0; i < 9; i++) A[i] *= scale;

    // ---- degree-8 Taylor via Paterson–Stockmeyer (4 matmuls) ----
    // exp(A) ~ (b0 I + b1 A + b2 A2 + b3 A3) + A4*(b4 I + b5 A + b6 A2 + b7 A3 + b8 A4)
    const float b2c = 0.5f;
    const float b3c = 1.6666666666666666e-01f;  // 1/6
    const float b4c = 4.1666666666666664e-02f;  // 1/24
    const float b5c = 8.3333333333333332e-03f;  // 1/120
    const float b6c = 1.3888888888888889e-03f;  // 1/720
    const float b7c = 1.9841269841269841e-04f;  // 1/5040
    const float b8c = 2.4801587301587302e-05f;  // 1/40320

    float A2[9], A3[9], A4[9];
    mat33_mul(A, A, A2);
    mat33_mul(A2, A, A3);
    mat33_mul(A2, A2, A4);

    float U[9], W[9];
    #pragma unroll
    for (int i = 0; i < 9; i++) {
        // low part: b1*A + b2*A2 + b3*A3  (+ b0*I on diag below)
        U[i] = fmaf(b3c, A3[i], fmaf(b2c, A2[i], A[i]));
        // high part: b5*A + b6*A2 + b7*A3 + b8*A4  (+ b4*I on diag below)
        W[i] = fmaf(b8c, A4[i], fmaf(b7c, A3[i], fmaf(b6c, A2[i], b5c * A[i])));
    }
    U[0] += 1.f; U[4] += 1.f; U[8] += 1.f;
    W[0] += b4c; W[4] += b4c; W[8] += b4c;

    float P[9];
    mat33_mul_acc(A4, W, U, P);   // P = U + A4*W

    // ---- repeated squaring: E = P^(2^s) ----
    for (int it = 0; it < s; it++) {
        float Q[9];
        mat33_mul(P, P, Q);
        #pragma unroll
        for (int i = 0; i < 9; i++) P[i] = Q[i];
    }

    // ---- y = E @ x[b] ----
    const float* xb = x + (size_t)b * 3;
    float x0 = xb[0], x1 = xb[1], x2 = xb[2];

    float* ob = out + (size_t)b * 3;
    ob[0] = fmaf(P[0], x0, fmaf(P[1], x1, P[2] * x2));
    ob[1] = fmaf(P[3], x0, fmaf(P[4], x1, P[5] * x2));
    ob[2] = fmaf(P[6], x0, fmaf(P[7], x1, P[8] * x2));
}

extern "C" void kernel_launch(void* const* d_in, const int* in_sizes, int n_in,
                              void* d_out, int out_size) {
    const float* c   = (const float*)d_in[0];   // (B, 6)
    const float* x   = (const float*)d_in[1];   // (B, 3, 1)
    const float* psi = (const float*)d_in[2];   // (6, 3, 3)
    float* out = (float*)d_out;                 // (B, 3, 1)

    int B = in_sizes[0] / MM;
    int threads = 256;
    int blocks = (B + threads - 1) / threads;
    transop_expm_kernel<<<blocks, threads>>>(c, x, psi, out, B);
}